// round 6
// baseline (speedup 1.0000x reference)
#include <cuda_runtime.h>

typedef unsigned long long ULL;

#define BB 256
#define TT 1024
#define FF 64
#define UU 128
#define G3 384   // 3*U

// ---------------- scratch buffers (no cudaMalloc allowed) ----------------
static __device__ float g_xw1[(size_t)BB * TT * G3];   // input proj layer1 [B,T,384]
static __device__ float g_seq1[(size_t)BB * TT * UU];  // layer1 hidden seq [B,T,128]
static __device__ float g_xw2[(size_t)BB * TT * G3];   // input proj layer2 [B,T,384]

// ---------------- helpers ----------------
__device__ __forceinline__ ULL fma2(ULL a, ULL b, ULL c) {
    ULL d;
    asm("fma.rn.f32x2 %0, %1, %2, %3;" : "=l"(d) : "l"(a), "l"(b), "l"(c));
    return d;
}
__device__ __forceinline__ ULL addp(ULL a, ULL b) {
    ULL d;
    asm("add.rn.f32x2 %0, %1, %2;" : "=l"(d) : "l"(a), "l"(b));
    return d;
}
__device__ __forceinline__ ULL pack2(float lo, float hi) {
    ULL d;
    asm("mov.b64 %0, {%1, %2};" : "=l"(d) : "f"(lo), "f"(hi));
    return d;
}
__device__ __forceinline__ float2 unpack2(ULL v) {
    float lo, hi;
    asm("mov.b64 {%0, %1}, %2;" : "=f"(lo), "=f"(hi) : "l"(v));
    return make_float2(lo, hi);
}
__device__ __forceinline__ float4 add4(float4 a, float4 b) {
    return make_float4(a.x + b.x, a.y + b.y, a.z + b.z, a.w + b.w);
}
__device__ __forceinline__ float sigm(float x) {
    return 1.0f / (1.0f + __expf(-x));
}

// =====================================================================
// GEMM: out[M,384] = X[M,K] @ W[K,384] + bias,  K = 4*KC (64 or 128)
// (unchanged — at its fp32 fma floor ~550us combined; tensor-core
//  rewrite is a later round)
// =====================================================================
template <int KC>
__global__ void __launch_bounds__(384, 1) gemm_kernel(
    const float* __restrict__ X, const float* __restrict__ W,
    const float* __restrict__ bias, float* __restrict__ out, int nblk)
{
    constexpr int K = 4 * KC;
    extern __shared__ char smem[];
    ulonglong2* Ws2   = (ulonglong2*)smem;
    float4*     Wf4   = (float4*)smem;
    ulonglong2* part2 = (ulonglong2*)(smem + (size_t)K * 1536);
    float4*     partf = (float4*)(smem + (size_t)K * 1536);
    ULL*        xp    = (ULL*)(smem + (size_t)K * 1536 + 24576);
    float2*     xpf   = (float2*)xp;

    const int t  = threadIdx.x;
    const int cq = t % 96;
    const int kg = t / 96;
    const int kbase = kg * KC;

    for (int i = t; i < K * 96; i += 384) Wf4[i] = ((const float4*)W)[i];
    float4 bq = ((const float4*)bias)[cq];
    ULL b01 = pack2(bq.x, bq.y), b23 = pack2(bq.z, bq.w);
    __syncthreads();

    for (int blk = blockIdx.x; blk < nblk; blk += gridDim.x) {
        const int row0 = blk * 4;
        for (int i = t; i < 4 * K; i += 384) {
            float v = X[(size_t)row0 * K + i];
            xpf[i] = make_float2(v, v);
        }
        __syncthreads();

        ULL a0[4], a1[4];
#pragma unroll
        for (int r = 0; r < 4; r++) {
            a0[r] = (kg == 0) ? b01 : 0ull;
            a1[r] = (kg == 0) ? b23 : 0ull;
        }
        const ulonglong2* Up = Ws2 + kbase * 96 + cq;
        const ULL* x0 = xp + kbase;
#pragma unroll
        for (int kk = 0; kk < KC; kk++) {
            ulonglong2 u = Up[kk * 96];
            ULL h;
            h = x0[kk];           a0[0] = fma2(u.x, h, a0[0]); a1[0] = fma2(u.y, h, a1[0]);
            h = x0[K + kk];       a0[1] = fma2(u.x, h, a0[1]); a1[1] = fma2(u.y, h, a1[1]);
            h = x0[2 * K + kk];   a0[2] = fma2(u.x, h, a0[2]); a1[2] = fma2(u.y, h, a1[2]);
            h = x0[3 * K + kk];   a0[3] = fma2(u.x, h, a0[3]); a1[3] = fma2(u.y, h, a1[3]);
        }
        ulonglong2* P = part2 + kg * 4 * 96 + cq;
#pragma unroll
        for (int r = 0; r < 4; r++) P[r * 96] = make_ulonglong2(a0[r], a1[r]);
        __syncthreads();

        {
            float4 s = partf[kg * 96 + cq];
#pragma unroll
            for (int kg2 = 1; kg2 < 4; kg2++)
                s = add4(s, partf[(kg2 * 4 + kg) * 96 + cq]);
            ((float4*)out)[(size_t)(row0 + kg) * 96 + cq] = s;
        }
        __syncthreads();
    }
}

// =====================================================================
// GRU scan v4: hybrid U placement. 128 CTAs x 2 rows, 256 threads.
// Thread (q in [0,64), kg = lane>>3) owns:
//   - registers: U[kg*32..+32, cols {2q,2q+1}] for gates z,r  (64 ULL = 128 regs)
//   - smem:      U_h (h-candidate gate third, 64KB) streamed per step
// Per step: h broadcast LDS + 192 fma2; shfl.bfly kg-reduction;
// in-thread gates; double-buffered h; one __syncthreads per step.
// =====================================================================
__global__ void __launch_bounds__(256, 1) scan_kernel(
    const float* __restrict__ xw,       // [B,T,384]
    const float* __restrict__ Urec,     // [128,384]
    const float* __restrict__ rbias,    // [384]
    float2* __restrict__ seqout,        // [B,T,64] float2 or null
    float2* __restrict__ hfin1,         // [B,64] float2
    float2* __restrict__ hfin2)         // optional second copy or null
{
    extern __shared__ char smem[];
    float* Uh = (float*)smem;                       // [128][128] = 65536 B
    const ULL* Uh64 = (const ULL*)smem;             // packed col-pair view
    ULL (*hp)[2][UU] = (ULL (*)[2][UU])(smem + 65536);  // [buf][row][k] (h,h), 4KB

    const int t    = threadIdx.x;
    const int lane = t & 31;
    const int w    = t >> 5;
    const int q    = (w << 3) | (lane & 7);    // 0..63  output pair
    const int kg   = lane >> 3;                // 0..3   k-slice
    const int kbase = kg * 32;
    const int row0 = blockIdx.x * 2;

    // ---- U_h (cols 256..383) into smem: Uh[k][c] = Urec[k][256+c]
    for (int i = t; i < UU * UU; i += 256) {
        int k = i >> 7, c = i & 127;
        Uh[i] = Urec[(size_t)k * G3 + 256 + c];
    }

    // ---- z,r gate U slice into registers: Ur[kk][g] = (U[k][g*128+2q], +1)
    ULL Ur[32][2];
#pragma unroll
    for (int kk = 0; kk < 32; kk++) {
#pragma unroll
        for (int g = 0; g < 2; g++) {
            float2 u = *(const float2*)(Urec + (size_t)(kbase + kk) * G3 + g * 128 + 2 * q);
            Ur[kk][g] = pack2(u.x, u.y);
        }
    }
    // recurrent bias (kg==0 lanes seed accumulators)
    ULL rb[3];
#pragma unroll
    for (int g = 0; g < 3; g++) {
        float2 bv = *(const float2*)(rbias + g * 128 + 2 * q);
        rb[g] = (kg == 0) ? pack2(bv.x, bv.y) : 0ull;
    }

    // zero h buffer 0
    hp[0][t >> 7][t & 127] = 0ull;
    float2 hprev[2] = {make_float2(0.f, 0.f), make_float2(0.f, 0.f)};
    __syncthreads();

    for (int step = 0; step < TT; ++step) {
        const int rbuf = step & 1;
        const ULL* h0 = &hp[rbuf][0][kbase];
        const ULL* h1 = &hp[rbuf][1][kbase];
        ULL (*hw)[UU] = hp[rbuf ^ 1];

        // prefetch xw for this step (global; consumed after mainloop)
        float2 xg[3][2];
#pragma unroll
        for (int g = 0; g < 3; g++) {
#pragma unroll
            for (int r = 0; r < 2; r++) {
                xg[g][r] = *(const float2*)(xw +
                    ((size_t)(row0 + r) * TT + step) * G3 + g * 128 + 2 * q);
            }
        }

        ULL az0 = rb[0], az1 = rb[0];
        ULL ar0 = rb[1], ar1 = rb[1];
        ULL ah0 = rb[2], ah1 = rb[2];

        const ulonglong2* h0p = (const ulonglong2*)h0;
        const ulonglong2* h1p = (const ulonglong2*)h1;
        const ULL* uhp = Uh64 + (size_t)kbase * 64 + q;   // stride 64 per k
#pragma unroll
        for (int j = 0; j < 16; j++) {
            ulonglong2 ha = h0p[j];           // (h,h) k=2j,2j+1 row0 (broadcast)
            ulonglong2 hb = h1p[j];           // row1
            ULL u0 = uhp[(2 * j) * 64];       // U_h[k=2j][2q..2q+1]
            ULL u1 = uhp[(2 * j + 1) * 64];
            az0 = fma2(Ur[2 * j][0],     ha.x, az0);
            az0 = fma2(Ur[2 * j + 1][0], ha.y, az0);
            az1 = fma2(Ur[2 * j][0],     hb.x, az1);
            az1 = fma2(Ur[2 * j + 1][0], hb.y, az1);
            ar0 = fma2(Ur[2 * j][1],     ha.x, ar0);
            ar0 = fma2(Ur[2 * j + 1][1], ha.y, ar0);
            ar1 = fma2(Ur[2 * j][1],     hb.x, ar1);
            ar1 = fma2(Ur[2 * j + 1][1], hb.y, ar1);
            ah0 = fma2(u0, ha.x, ah0);
            ah0 = fma2(u1, ha.y, ah0);
            ah1 = fma2(u0, hb.x, ah1);
            ah1 = fma2(u1, hb.y, ah1);
        }

        // kg-reduction: butterfly xor 8, xor 16
        ULL acc[3][2] = {{az0, az1}, {ar0, ar1}, {ah0, ah1}};
#pragma unroll
        for (int g = 0; g < 3; g++)
#pragma unroll
            for (int r = 0; r < 2; r++)
                acc[g][r] = addp(acc[g][r], __shfl_xor_sync(0xffffffffu, acc[g][r], 8));
#pragma unroll
        for (int g = 0; g < 3; g++)
#pragma unroll
            for (int r = 0; r < 2; r++)
                acc[g][r] = addp(acc[g][r], __shfl_xor_sync(0xffffffffu, acc[g][r], 16));

        // gates (all lanes compute; kg==0 lanes store)
#pragma unroll
        for (int r = 0; r < 2; r++) {
            float2 az = unpack2(acc[0][r]);
            float2 ar = unpack2(acc[1][r]);
            float2 ah = unpack2(acc[2][r]);
            float z0 = sigm(xg[0][r].x + az.x);
            float z1 = sigm(xg[0][r].y + az.y);
            float r0 = sigm(xg[1][r].x + ar.x);
            float r1 = sigm(xg[1][r].y + ar.y);
            float hh0 = fmaxf(xg[2][r].x + r0 * ah.x, 0.0f);
            float hh1 = fmaxf(xg[2][r].y + r1 * ah.y, 0.0f);
            float hn0 = z0 * hprev[r].x + (1.0f - z0) * hh0;
            float hn1 = z1 * hprev[r].y + (1.0f - z1) * hh1;
            hprev[r] = make_float2(hn0, hn1);
            if (kg == 0) {
                *(ulonglong2*)&hw[r][2 * q] =
                    make_ulonglong2(pack2(hn0, hn0), pack2(hn1, hn1));
                if (seqout)
                    seqout[((size_t)(row0 + r) * TT + step) * 64 + q] =
                        make_float2(hn0, hn1);
            }
        }
        __syncthreads();
    }

    if (kg == 0) {
#pragma unroll
        for (int r = 0; r < 2; r++) {
            hfin1[(size_t)(row0 + r) * 64 + q] = hprev[r];
            if (hfin2) hfin2[(size_t)(row0 + r) * 64 + q] = hprev[r];
        }
    }
}

// =====================================================================
// launch
// =====================================================================
extern "C" void kernel_launch(void* const* d_in, const int* in_sizes, int n_in,
                              void* d_out, int out_size)
{
    (void)in_sizes; (void)n_in; (void)out_size;
    const float* input = (const float*)d_in[0];  // [256,1024,64]
    const float* W1    = (const float*)d_in[1];  // [64,384]
    const float* U1    = (const float*)d_in[2];  // [128,384]
    const float* b1    = (const float*)d_in[3];  // [2,384]
    const float* W2    = (const float*)d_in[4];  // [128,384]
    const float* U2    = (const float*)d_in[5];  // [128,384]
    const float* b2    = (const float*)d_in[6];  // [2,384]
    float* out = (float*)d_out;                  // [3*256*128]: x | state1 | state2

    float *xw1, *seq1, *xw2;
    cudaGetSymbolAddress((void**)&xw1,  g_xw1);
    cudaGetSymbolAddress((void**)&seq1, g_seq1);
    cudaGetSymbolAddress((void**)&xw2,  g_xw2);

    const int SMEM_G1 = 64 * 1536 + 24576 + 2048;    // 124928
    const int SMEM_G2 = 128 * 1536 + 24576 + 4096;   // 225280
    const int SMEM_S  = 65536 + 4096;                // 69632

    cudaFuncSetAttribute(gemm_kernel<16>, cudaFuncAttributeMaxDynamicSharedMemorySize, SMEM_G1);
    cudaFuncSetAttribute(gemm_kernel<32>, cudaFuncAttributeMaxDynamicSharedMemorySize, SMEM_G2);
    cudaFuncSetAttribute(scan_kernel,     cudaFuncAttributeMaxDynamicSharedMemorySize, SMEM_S);

    const int nblk = (BB * TT) / 4;  // 65536 row-blocks of 4

    // Layer 1 input projection: xw1 = input @ W1 + b1[0]
    gemm_kernel<16><<<148, 384, SMEM_G1>>>(input, W1, b1, xw1, nblk);
    // Layer 1 scan: seq1, state1
    scan_kernel<<<128, 256, SMEM_S>>>(xw1, U1, b1 + G3,
                                      (float2*)seq1,
                                      (float2*)(out + 32768), nullptr);
    // Layer 2 input projection: xw2 = seq1 @ W2 + b2[0]
    gemm_kernel<32><<<148, 384, SMEM_G2>>>(seq1, W2, b2, xw2, nblk);
    // Layer 2 scan: x (== state2)
    scan_kernel<<<128, 256, SMEM_S>>>(xw2, U2, b2 + G3,
                                      nullptr,
                                      (float2*)out, (float2*)(out + 65536));
}